// round 15
// baseline (speedup 1.0000x reference)
#include <cuda_runtime.h>
#include <cuda_bf16.h>

// B=8, C=128, IC=64, H=W=64, N=4096, M=1024 (pooled 32x32)

__device__ float g_p[8][1024];
__device__ float g_t[8][4096];
__device__ float g_xg[8][1024][64];
__device__ float g_psort[8][1024];
__device__ int   g_perm[8][1024];
__device__ unsigned short g_k[8][4096];   // precomputed binsearch result per pixel
__device__ float2 g_S12[8][1025][64];     // interleaved (S1,S2)
__device__ unsigned g_w2b[4096];          // w2 packed bf16x2 [co][ii]

// ---- helpers --------------------------------------------------------------
__device__ __forceinline__ unsigned pbf2(float lo, float hi) {
    unsigned r; asm("cvt.rn.bf16x2.f32 %0, %1, %2;" : "=r"(r) : "f"(hi), "f"(lo));
    return r;
}
__device__ __forceinline__ void mma16816(float* d, unsigned a0, unsigned a1,
                                         unsigned a2, unsigned a3,
                                         unsigned b0, unsigned b1) {
    asm("mma.sync.aligned.m16n8k16.row.col.f32.bf16.bf16.f32 "
        "{%0,%1,%2,%3}, {%4,%5,%6,%7}, {%8,%9}, {%0,%1,%2,%3};"
        : "+f"(d[0]), "+f"(d[1]), "+f"(d[2]), "+f"(d[3])
        : "r"(a0), "r"(a1), "r"(a2), "r"(a3), "r"(b0), "r"(b1));
}

// ---------------------------------------------------------------------------
// K1: fused conv1+conv4 via bf16 mma.sync, in-register maxpool,
//     + folded conv3 scalar t (wtp folded per block).  (R9 verbatim)
// ---------------------------------------------------------------------------
#define SWS 68
#define SXS 136
__global__ void __launch_bounds__(256, 2)
k1_conv(const float* __restrict__ x,
        const float* __restrict__ w1, const float* __restrict__ b1,
        const float* __restrict__ w3, const float* __restrict__ b3,
        const float* __restrict__ w4, const float* __restrict__ b4,
        const float* __restrict__ w5) {
    extern __shared__ unsigned smu[];
    unsigned* sWb  = smu;                    // 128*68
    unsigned* sXb  = smu + 128 * SWS;        // 64*136
    float* sBias = (float*)(sXb + 64 * SXS); // 128
    float* sWp   = sBias + 128;              // 64
    float* sWtp  = sWp + 64;                 // 132
    float* sPred = sWtp + 132;               // 4*32

    const int tid = threadIdx.x;
    const int pr  = blockIdx.x;
    const int b   = blockIdx.y;

    const float4* w1v = (const float4*)w1;
    const float4* w4v = (const float4*)w4;
    #pragma unroll
    for (int k = 0; k < 16; k++) {
        int v  = tid + k * 256;
        int oc = v >> 5, c4 = v & 31;
        float4 f = (oc < 64) ? w1v[oc * 32 + c4] : w4v[(oc - 64) * 32 + c4];
        *(uint2*)&sWb[oc * SWS + c4 * 2] = make_uint2(pbf2(f.x, f.y), pbf2(f.z, f.w));
    }
    const float4* xv = (const float4*)x;
    #pragma unroll
    for (int it = 0; it < 8; it++) {
        int v   = tid + it * 256;
        int cc  = v >> 5, u = v & 31;
        int r01 = u >> 4, c4 = u & 15;
        float4 fa = xv[((b * 128 + 2 * cc) * 64 + (2 * pr + r01)) * 16 + c4];
        float4 fb = xv[((b * 128 + 2 * cc + 1) * 64 + (2 * pr + r01)) * 16 + c4];
        uint4 q;
        q.x = pbf2(fa.x, fb.x); q.y = pbf2(fa.y, fb.y);
        q.z = pbf2(fa.z, fb.z); q.w = pbf2(fa.w, fb.w);
        *(uint4*)&sXb[cc * SXS + r01 * 64 + c4 * 4] = q;
    }
    if (tid < 128) {
        float acc = 0.f;
        #pragma unroll 16
        for (int i = 0; i < 64; i++) acc = fmaf(w5[i], w3[i * 128 + tid], acc);
        sWtp[tid] = acc;
        sBias[tid] = (tid < 64) ? b1[tid] : b4[tid - 64];
    } else if (tid < 160) {
        int l = tid - 128;
        float s = fmaf(w5[l], b3[l], w5[l + 32] * b3[l + 32]);
        #pragma unroll
        for (int d = 16; d >= 1; d >>= 1)
            s += __shfl_xor_sync(0xffffffffu, s, d);
        if (l == 0) sWtp[128] = s;
    }
    if (tid < 64) sWp[tid] = w5[64 + tid];
    __syncthreads();

    const int w    = tid >> 5;
    const int lane = tid & 31;
    const int g    = lane >> 2;
    const int m4   = lane & 3;
    const int ocb  = w * 16;

    float acc[16][4];
    #pragma unroll
    for (int t = 0; t < 16; t++)
        #pragma unroll
        for (int r = 0; r < 4; r++) acc[t][r] = 0.f;

    #pragma unroll
    for (int s = 0; s < 8; s++) {
        const int cc0 = s * 8;
        unsigned a0 = sWb[(ocb + g)     * SWS + cc0 + m4];
        unsigned a1 = sWb[(ocb + g + 8) * SWS + cc0 + m4];
        unsigned a2 = sWb[(ocb + g)     * SWS + cc0 + 4 + m4];
        unsigned a3 = sWb[(ocb + g + 8) * SWS + cc0 + 4 + m4];
        #pragma unroll
        for (int t = 0; t < 16; t++) {
            unsigned b0 = sXb[(cc0 + m4)     * SXS + t * 8 + g];
            unsigned b1 = sXb[(cc0 + 4 + m4) * SXS + t * 8 + g];
            mma16816(acc[t], a0, a1, a2, a3, b0, b1);
        }
    }

    if (tid < 128) {
        float a = sWtp[128];
        #pragma unroll 8
        for (int cc = 0; cc < 64; cc++) {
            unsigned u = sXb[cc * SXS + tid];
            __nv_bfloat162 h = *reinterpret_cast<__nv_bfloat162*>(&u);
            float2 f = __bfloat1622float2(h);
            a = fmaf(sWtp[2 * cc], f.x, a);
            a = fmaf(sWtp[2 * cc + 1], f.y, a);
        }
        int n = (2 * pr + (tid >> 6)) * 64 + (tid & 63);
        g_t[b][n] = a;
    }

    float pg[8], pg8[8];
    #pragma unroll
    for (int t = 0; t < 8; t++) {
        pg[t]  = fmaxf(fmaxf(acc[t][0], acc[t][1]), fmaxf(acc[t + 8][0], acc[t + 8][1]));
        pg8[t] = fmaxf(fmaxf(acc[t][2], acc[t][3]), fmaxf(acc[t + 8][2], acc[t + 8][3]));
    }

    if (w < 4) {  // xg path: oc 0..63
        int oc0 = ocb + g, oc1 = ocb + g + 8;
        float b0v = sBias[oc0], b1v = sBias[oc1];
        #pragma unroll
        for (int t = 0; t < 8; t++) {
            int mb = pr * 32 + t * 4 + m4;
            g_xg[b][mb][oc0] = pg[t]  + b0v;
            g_xg[b][mb][oc1] = pg8[t] + b1v;
        }
    } else {      // p path
        int oc0 = ocb + g, oc1 = ocb + g + 8;
        float wp0 = sWp[oc0 - 64], wp1 = sWp[oc1 - 64];
        float b0v = sBias[oc0], b1v = sBias[oc1];
        float part[8];
        #pragma unroll
        for (int t = 0; t < 8; t++)
            part[t] = fmaf(wp0, pg[t] + b0v, wp1 * (pg8[t] + b1v));
        #pragma unroll
        for (int d = 4; d < 32; d <<= 1) {
            #pragma unroll
            for (int t = 0; t < 8; t++)
                part[t] += __shfl_xor_sync(0xffffffffu, part[t], d);
        }
        if (lane < 4) {
            #pragma unroll
            for (int t = 0; t < 8; t++)
                sPred[(w - 4) * 32 + t * 4 + lane] = part[t];
        }
    }
    __syncthreads();
    if (tid < 32) {
        float pv = sPred[tid] + sPred[32 + tid] + sPred[64 + tid] + sPred[96 + tid];
        g_p[b][pr * 32 + tid] = pv;
    }
}

// ---------------------------------------------------------------------------
// K2a: bitonic sort (ping-pong smem) + w2 bf16 pack + PER-PIXEL BINSEARCH
//      (4096 searches per batch on the already-resident sorted array).
// ---------------------------------------------------------------------------
__global__ void __launch_bounds__(1024) k2_sort(const float* __restrict__ w2) {
    __shared__ unsigned long long skA[1024], skB[1024];
    const int b = blockIdx.x, tid = threadIdx.x;

    {
        int u = b * 512 + tid;
        if (tid < 512) {
            float2 f = ((const float2*)w2)[u];
            g_w2b[u] = pbf2(f.x, f.y);
        }
    }

    float v = g_p[b][tid];
    unsigned u = __float_as_uint(v);
    u = (u & 0x80000000u) ? ~u : (u | 0x80000000u);
    unsigned long long key = ((unsigned long long)u << 32) | (unsigned)tid;

    int pb = 0;
    #pragma unroll
    for (int k = 2; k <= 1024; k <<= 1) {
        const bool up = ((tid & k) == 0);
        for (int j = k >> 1; j >= 32; j >>= 1) {
            unsigned long long* buf = pb ? skB : skA;
            buf[tid] = key;
            __syncthreads();
            unsigned long long ok = buf[tid ^ j];
            pb ^= 1;
            bool takeMin = (((tid & j) == 0) == up);
            if ((key > ok) == takeMin) key = ok;
        }
        #pragma unroll
        for (int j = ((k >> 1) < 16 ? (k >> 1) : 16); j >= 1; j >>= 1) {
            unsigned long long ok = __shfl_xor_sync(0xffffffffu, key, j);
            bool takeMin = (((tid & j) == 0) == up);
            if ((key > ok) == takeMin) key = ok;
        }
    }
    int m = (int)(key & 1023u);
    float pv = g_p[b][m];
    g_perm[b][tid]  = m;
    g_psort[b][tid] = pv;

    // ---- per-pixel binsearch on smem-resident sorted values ----
    __syncthreads();                 // all smem stage reads done
    float* sps = (float*)skA;        // 4KB
    sps[tid] = pv;
    __syncthreads();
    #pragma unroll
    for (int qq = 0; qq < 4; qq++) {
        int n = tid + qq * 1024;
        float keyn = -g_t[b][n];
        int lo = 0, hi = 1024;
        while (lo < hi) { int mid = (lo + hi) >> 1; if (sps[mid] > keyn) hi = mid; else lo = mid + 1; }
        g_k[b][n] = (unsigned short)lo;
    }
}

// ---------------------------------------------------------------------------
// K2b: suffix scan over xg, 256 threads x 4 j x 4 channels  (R9 verbatim)
// ---------------------------------------------------------------------------
__global__ void __launch_bounds__(256) k2_scan() {
    __shared__ float sm1[4][8], sm2[4][8];
    const int b = blockIdx.y, ig = blockIdx.x;
    const int tid = threadIdx.x, lane = tid & 31, w = tid >> 5;
    const int j0 = 4 * tid;

    if (tid == 0) {
        float2* z = &g_S12[b][1024][ig * 4];
        *(float4*)z       = make_float4(0.f, 0.f, 0.f, 0.f);
        *(float4*)(z + 2) = make_float4(0.f, 0.f, 0.f, 0.f);
    }

    const int4   pm = ((const int4*)g_perm[b])[tid];
    const float4 ps = ((const float4*)g_psort[b])[tid];

    float4 v0 = *(const float4*)&g_xg[b][pm.x][ig * 4];
    float4 v1 = *(const float4*)&g_xg[b][pm.y][ig * 4];
    float4 v2 = *(const float4*)&g_xg[b][pm.z][ig * 4];
    float4 v3 = *(const float4*)&g_xg[b][pm.w][ig * 4];
    float vv[4][4] = {{v0.x, v0.y, v0.z, v0.w}, {v1.x, v1.y, v1.z, v1.w},
                      {v2.x, v2.y, v2.z, v2.w}, {v3.x, v3.y, v3.z, v3.w}};
    float pp[4] = {ps.x, ps.y, ps.z, ps.w};

    float s1[4], s2[4];
    #pragma unroll
    for (int c = 0; c < 4; c++) {
        s1[c] = vv[0][c] + vv[1][c] + vv[2][c] + vv[3][c];
        s2[c] = fmaf(pp[0], vv[0][c], fmaf(pp[1], vv[1][c],
                fmaf(pp[2], vv[2][c], pp[3] * vv[3][c])));
    }

    #pragma unroll
    for (int d = 1; d < 32; d <<= 1) {
        bool take = (lane + d < 32);
        #pragma unroll
        for (int c = 0; c < 4; c++) {
            float t1 = __shfl_down_sync(0xffffffffu, s1[c], d);
            float t2 = __shfl_down_sync(0xffffffffu, s2[c], d);
            if (take) { s1[c] += t1; s2[c] += t2; }
        }
    }
    if (lane == 0) {
        #pragma unroll
        for (int c = 0; c < 4; c++) { sm1[c][w] = s1[c]; sm2[c][w] = s2[c]; }
    }
    __syncthreads();
    #pragma unroll
    for (int c = 0; c < 4; c++) {
        float c1 = 0.f, c2 = 0.f;
        #pragma unroll
        for (int w2i = 0; w2i < 8; w2i++)
            if (w2i > w) { c1 += sm1[c][w2i]; c2 += sm2[c][w2i]; }
        s1[c] += c1; s2[c] += c2;
    }

    float2* base = &g_S12[b][j0][ig * 4];
    #pragma unroll
    for (int k = 0; k < 4; k++) {
        float4 oa = make_float4(s1[0], s2[0], s1[1], s2[1]);
        float4 ob = make_float4(s1[2], s2[2], s1[3], s2[3]);
        float2* dst = base + (long)k * 64;
        *(float4*)dst       = oa;
        *(float4*)(dst + 2) = ob;
        if (k < 3) {
            #pragma unroll
            for (int c = 0; c < 4; c++) {
                s1[c] -= vv[k][c];
                s2[c] = fmaf(-pp[k], vv[k][c], s2[c]);
            }
        }
    }
}

// ---------------------------------------------------------------------------
// K3: warp-specialized pipeline, NO binsearch (uses g_k), no psort/t stage.
//     512 threads: warps 0-7 consume (MMA+epi), 8-15 produce (gather+ybuild).
//     Double-buffered 64-px tiles, 128 px/block, grid (32,8)=256 blocks.
// ---------------------------------------------------------------------------
#define W2S 36
#define YB 69
__global__ void __launch_bounds__(512, 2)
k3_out(const float* __restrict__ x,
       const float* __restrict__ b2,
       const float* __restrict__ bg, const float* __restrict__ bb,
       const float* __restrict__ bm, const float* __restrict__ bv,
       float* __restrict__ out) {
    extern __shared__ float sm[];
    unsigned* sW2b = (unsigned*)sm;              // 128*36 = 4608
    unsigned* sYb  = sW2b + 128 * W2S;           // 2 * 32*69 = 4416
    float*    sA   = (float*)(sYb + 2 * 32 * YB);// 128
    float*    sB   = sA + 128;                   // 128

    const int tid = threadIdx.x;
    const int b   = blockIdx.y;
    const int n00 = blockIdx.x * 128;
    const bool producer = tid >= 256;

    if (!producer) {
        // stage w2 + BN constants
        const uint4* w2b4 = (const uint4*)g_w2b;     // 1024 uint4
        #pragma unroll
        for (int k = 0; k < 4; k++) {
            int v = tid + k * 256;
            int co = v >> 3, q4 = v & 7;
            *(uint4*)&sW2b[co * W2S + q4 * 4] = w2b4[v];
        }
        if (tid < 128) {
            float inv = rsqrtf(bv[tid] + 1e-5f);
            float al  = bg[tid] * inv;
            sA[tid] = al;
            sB[tid] = (b2[tid] - bm[tid]) * al + bb[tid];
        }
    } else {
        // prologue: fill tile 0 into buf 0 (no staged deps needed)
        int pt = tid - 256;
        int n = pt >> 2, q = pt & 3;
        float t = g_t[b][n00 + n];
        int lo = g_k[b][n00 + n];
        const float4* s4 = (const float4*)&g_S12[b][lo][q * 16];
        unsigned* dst = sYb;
        #pragma unroll
        for (int r = 0; r < 8; r++) {
            float4 s = s4[r];
            float y0 = fmaf(t, s.x, s.y) * (1.0f / 1024.0f);
            float y1 = fmaf(t, s.z, s.w) * (1.0f / 1024.0f);
            dst[(q * 8 + r) * YB + n] = pbf2(y0, y1);
        }
    }
    __syncthreads();

    const int w    = tid >> 5;
    const int lane = tid & 31;
    const int g    = lane >> 2;
    const int m4   = lane & 3;

    #pragma unroll 1
    for (int tt = 0; tt < 2; tt++) {
        if (!producer) {
            const unsigned* buf = sYb + (tt & 1) * 32 * YB;
            const int ocb = w * 16;
            float acc[8][4];
            #pragma unroll
            for (int t = 0; t < 8; t++)
                #pragma unroll
                for (int r = 0; r < 4; r++) acc[t][r] = 0.f;

            #pragma unroll
            for (int s = 0; s < 4; s++) {
                const int ii0 = s * 8;
                unsigned a0 = sW2b[(ocb + g)     * W2S + ii0 + m4];
                unsigned a1 = sW2b[(ocb + g + 8) * W2S + ii0 + m4];
                unsigned a2 = sW2b[(ocb + g)     * W2S + ii0 + 4 + m4];
                unsigned a3 = sW2b[(ocb + g + 8) * W2S + ii0 + 4 + m4];
                #pragma unroll
                for (int t = 0; t < 8; t++) {
                    unsigned b0 = buf[(ii0 + m4)     * YB + t * 8 + g];
                    unsigned b1 = buf[(ii0 + 4 + m4) * YB + t * 8 + g];
                    mma16816(acc[t], a0, a1, a2, a3, b0, b1);
                }
            }

            const int co0 = ocb + g, co1 = ocb + g + 8;
            const float A0 = sA[co0], B0 = sB[co0];
            const float A1 = sA[co1], B1 = sB[co1];
            const int base0 = ((b * 128 + co0) << 12) + n00 + tt * 64;
            const int base1 = ((b * 128 + co1) << 12) + n00 + tt * 64;
            #pragma unroll
            for (int t = 0; t < 8; t++) {
                int n = t * 8 + 2 * m4;
                float2 x0 = *(const float2*)&x[base0 + n];
                float2 x1 = *(const float2*)&x[base1 + n];
                float2 o0, o1;
                o0.x = fmaf(acc[t][0], A0, B0) + x0.x;
                o0.y = fmaf(acc[t][1], A0, B0) + x0.y;
                o1.x = fmaf(acc[t][2], A1, B1) + x1.x;
                o1.y = fmaf(acc[t][3], A1, B1) + x1.y;
                *(float2*)&out[base0 + n] = o0;
                *(float2*)&out[base1 + n] = o1;
            }
        } else if (tt == 0) {
            // produce tile 1 into buf 1
            int pt = tid - 256;
            int n = pt >> 2, q = pt & 3;
            float t = g_t[b][n00 + 64 + n];
            int lo = g_k[b][n00 + 64 + n];
            const float4* s4 = (const float4*)&g_S12[b][lo][q * 16];
            unsigned* dst = sYb + 32 * YB;
            #pragma unroll
            for (int r = 0; r < 8; r++) {
                float4 s = s4[r];
                float y0 = fmaf(t, s.x, s.y) * (1.0f / 1024.0f);
                float y1 = fmaf(t, s.z, s.w) * (1.0f / 1024.0f);
                dst[(q * 8 + r) * YB + n] = pbf2(y0, y1);
            }
        }
        __syncthreads();
    }
}

// ---------------------------------------------------------------------------
extern "C" void kernel_launch(void* const* d_in, const int* in_sizes, int n_in,
                              void* d_out, int out_size) {
    const float* x  = (const float*)d_in[0];
    const float* w1 = (const float*)d_in[1];
    const float* b1 = (const float*)d_in[2];
    const float* w3 = (const float*)d_in[3];
    const float* b3 = (const float*)d_in[4];
    const float* w4 = (const float*)d_in[5];
    const float* b4 = (const float*)d_in[6];
    const float* w5 = (const float*)d_in[7];
    const float* w2 = (const float*)d_in[8];
    const float* b2 = (const float*)d_in[9];
    const float* bg = (const float*)d_in[10];
    const float* bb = (const float*)d_in[11];
    const float* bm = (const float*)d_in[12];
    const float* bv = (const float*)d_in[13];
    float* out = (float*)d_out;

    const int k1_smem = (128 * SWS + 64 * SXS) * 4 + (128 + 64 + 132 + 128) * 4;
    const int k3_smem = (128 * W2S + 2 * 32 * YB) * 4 + (128 + 128) * 4;
    cudaFuncSetAttribute(k1_conv, cudaFuncAttributeMaxDynamicSharedMemorySize, k1_smem);
    cudaFuncSetAttribute(k3_out,  cudaFuncAttributeMaxDynamicSharedMemorySize, k3_smem);

    k1_conv<<<dim3(32, 8), 256, k1_smem>>>(x, w1, b1, w3, b3, w4, b4, w5);
    k2_sort<<<8, 1024>>>(w2);
    k2_scan<<<dim3(16, 8), 256>>>();
    k3_out<<<dim3(32, 8), 512, k3_smem>>>(x, b2, bg, bb, bm, bv, out);
}

// round 16
// speedup vs baseline: 1.1222x; 1.1222x over previous
#include <cuda_runtime.h>
#include <cuda_bf16.h>

// B=8, C=128, IC=64, H=W=64, N=4096, M=1024 (pooled 32x32)

__device__ float g_p[8][1024];
__device__ float g_t[8][4096];
__device__ float g_xg[8][1024][64];
__device__ float g_psort[8][1024];
__device__ int   g_perm[8][1024];
__device__ unsigned short g_k[8][4096];   // precomputed binsearch result per pixel
__device__ float2 g_S12[8][1025][64];     // interleaved (S1,S2)
__device__ unsigned g_w2b[4096];          // w2 packed bf16x2 [co][ii]

// ---- helpers --------------------------------------------------------------
__device__ __forceinline__ unsigned pbf2(float lo, float hi) {
    unsigned r; asm("cvt.rn.bf16x2.f32 %0, %1, %2;" : "=r"(r) : "f"(hi), "f"(lo));
    return r;
}
__device__ __forceinline__ void mma16816(float* d, unsigned a0, unsigned a1,
                                         unsigned a2, unsigned a3,
                                         unsigned b0, unsigned b1) {
    asm("mma.sync.aligned.m16n8k16.row.col.f32.bf16.bf16.f32 "
        "{%0,%1,%2,%3}, {%4,%5,%6,%7}, {%8,%9}, {%0,%1,%2,%3};"
        : "+f"(d[0]), "+f"(d[1]), "+f"(d[2]), "+f"(d[3])
        : "r"(a0), "r"(a1), "r"(a2), "r"(a3), "r"(b0), "r"(b1));
}

// ---------------------------------------------------------------------------
// K1: fused conv1+conv4 via bf16 mma.sync, in-register maxpool,
//     + folded conv3 scalar t (wtp folded per block).  (R9 verbatim)
// ---------------------------------------------------------------------------
#define SWS 68
#define SXS 136
__global__ void __launch_bounds__(256, 2)
k1_conv(const float* __restrict__ x,
        const float* __restrict__ w1, const float* __restrict__ b1,
        const float* __restrict__ w3, const float* __restrict__ b3,
        const float* __restrict__ w4, const float* __restrict__ b4,
        const float* __restrict__ w5) {
    extern __shared__ unsigned smu[];
    unsigned* sWb  = smu;                    // 128*68
    unsigned* sXb  = smu + 128 * SWS;        // 64*136
    float* sBias = (float*)(sXb + 64 * SXS); // 128
    float* sWp   = sBias + 128;              // 64
    float* sWtp  = sWp + 64;                 // 132
    float* sPred = sWtp + 132;               // 4*32

    const int tid = threadIdx.x;
    const int pr  = blockIdx.x;
    const int b   = blockIdx.y;

    const float4* w1v = (const float4*)w1;
    const float4* w4v = (const float4*)w4;
    #pragma unroll
    for (int k = 0; k < 16; k++) {
        int v  = tid + k * 256;
        int oc = v >> 5, c4 = v & 31;
        float4 f = (oc < 64) ? w1v[oc * 32 + c4] : w4v[(oc - 64) * 32 + c4];
        *(uint2*)&sWb[oc * SWS + c4 * 2] = make_uint2(pbf2(f.x, f.y), pbf2(f.z, f.w));
    }
    const float4* xv = (const float4*)x;
    #pragma unroll
    for (int it = 0; it < 8; it++) {
        int v   = tid + it * 256;
        int cc  = v >> 5, u = v & 31;
        int r01 = u >> 4, c4 = u & 15;
        float4 fa = xv[((b * 128 + 2 * cc) * 64 + (2 * pr + r01)) * 16 + c4];
        float4 fb = xv[((b * 128 + 2 * cc + 1) * 64 + (2 * pr + r01)) * 16 + c4];
        uint4 q;
        q.x = pbf2(fa.x, fb.x); q.y = pbf2(fa.y, fb.y);
        q.z = pbf2(fa.z, fb.z); q.w = pbf2(fa.w, fb.w);
        *(uint4*)&sXb[cc * SXS + r01 * 64 + c4 * 4] = q;
    }
    if (tid < 128) {
        float acc = 0.f;
        #pragma unroll 16
        for (int i = 0; i < 64; i++) acc = fmaf(w5[i], w3[i * 128 + tid], acc);
        sWtp[tid] = acc;
        sBias[tid] = (tid < 64) ? b1[tid] : b4[tid - 64];
    } else if (tid < 160) {
        int l = tid - 128;
        float s = fmaf(w5[l], b3[l], w5[l + 32] * b3[l + 32]);
        #pragma unroll
        for (int d = 16; d >= 1; d >>= 1)
            s += __shfl_xor_sync(0xffffffffu, s, d);
        if (l == 0) sWtp[128] = s;
    }
    if (tid < 64) sWp[tid] = w5[64 + tid];
    __syncthreads();

    const int w    = tid >> 5;
    const int lane = tid & 31;
    const int g    = lane >> 2;
    const int m4   = lane & 3;
    const int ocb  = w * 16;

    float acc[16][4];
    #pragma unroll
    for (int t = 0; t < 16; t++)
        #pragma unroll
        for (int r = 0; r < 4; r++) acc[t][r] = 0.f;

    #pragma unroll
    for (int s = 0; s < 8; s++) {
        const int cc0 = s * 8;
        unsigned a0 = sWb[(ocb + g)     * SWS + cc0 + m4];
        unsigned a1 = sWb[(ocb + g + 8) * SWS + cc0 + m4];
        unsigned a2 = sWb[(ocb + g)     * SWS + cc0 + 4 + m4];
        unsigned a3 = sWb[(ocb + g + 8) * SWS + cc0 + 4 + m4];
        #pragma unroll
        for (int t = 0; t < 16; t++) {
            unsigned b0 = sXb[(cc0 + m4)     * SXS + t * 8 + g];
            unsigned b1 = sXb[(cc0 + 4 + m4) * SXS + t * 8 + g];
            mma16816(acc[t], a0, a1, a2, a3, b0, b1);
        }
    }

    if (tid < 128) {
        float a = sWtp[128];
        #pragma unroll 8
        for (int cc = 0; cc < 64; cc++) {
            unsigned u = sXb[cc * SXS + tid];
            __nv_bfloat162 h = *reinterpret_cast<__nv_bfloat162*>(&u);
            float2 f = __bfloat1622float2(h);
            a = fmaf(sWtp[2 * cc], f.x, a);
            a = fmaf(sWtp[2 * cc + 1], f.y, a);
        }
        int n = (2 * pr + (tid >> 6)) * 64 + (tid & 63);
        g_t[b][n] = a;
    }

    float pg[8], pg8[8];
    #pragma unroll
    for (int t = 0; t < 8; t++) {
        pg[t]  = fmaxf(fmaxf(acc[t][0], acc[t][1]), fmaxf(acc[t + 8][0], acc[t + 8][1]));
        pg8[t] = fmaxf(fmaxf(acc[t][2], acc[t][3]), fmaxf(acc[t + 8][2], acc[t + 8][3]));
    }

    if (w < 4) {  // xg path: oc 0..63
        int oc0 = ocb + g, oc1 = ocb + g + 8;
        float b0v = sBias[oc0], b1v = sBias[oc1];
        #pragma unroll
        for (int t = 0; t < 8; t++) {
            int mb = pr * 32 + t * 4 + m4;
            g_xg[b][mb][oc0] = pg[t]  + b0v;
            g_xg[b][mb][oc1] = pg8[t] + b1v;
        }
    } else {      // p path
        int oc0 = ocb + g, oc1 = ocb + g + 8;
        float wp0 = sWp[oc0 - 64], wp1 = sWp[oc1 - 64];
        float b0v = sBias[oc0], b1v = sBias[oc1];
        float part[8];
        #pragma unroll
        for (int t = 0; t < 8; t++)
            part[t] = fmaf(wp0, pg[t] + b0v, wp1 * (pg8[t] + b1v));
        #pragma unroll
        for (int d = 4; d < 32; d <<= 1) {
            #pragma unroll
            for (int t = 0; t < 8; t++)
                part[t] += __shfl_xor_sync(0xffffffffu, part[t], d);
        }
        if (lane < 4) {
            #pragma unroll
            for (int t = 0; t < 8; t++)
                sPred[(w - 4) * 32 + t * 4 + lane] = part[t];
        }
    }
    __syncthreads();
    if (tid < 32) {
        float pv = sPred[tid] + sPred[32 + tid] + sPred[64 + tid] + sPred[96 + tid];
        g_p[b][pr * 32 + tid] = pv;
    }
}

// ---------------------------------------------------------------------------
// K2a: bitonic sort (ping-pong smem) + w2 bf16 pack [co][ii]  (R9 verbatim)
// ---------------------------------------------------------------------------
__global__ void __launch_bounds__(1024) k2_sort(const float* __restrict__ w2) {
    __shared__ unsigned long long skA[1024], skB[1024];
    const int b = blockIdx.x, tid = threadIdx.x;

    {
        int u = b * 512 + tid;
        if (tid < 512) {
            float2 f = ((const float2*)w2)[u];
            g_w2b[u] = pbf2(f.x, f.y);
        }
    }

    float v = g_p[b][tid];
    unsigned u = __float_as_uint(v);
    u = (u & 0x80000000u) ? ~u : (u | 0x80000000u);
    unsigned long long key = ((unsigned long long)u << 32) | (unsigned)tid;

    int pb = 0;
    #pragma unroll
    for (int k = 2; k <= 1024; k <<= 1) {
        const bool up = ((tid & k) == 0);
        for (int j = k >> 1; j >= 32; j >>= 1) {
            unsigned long long* buf = pb ? skB : skA;
            buf[tid] = key;
            __syncthreads();
            unsigned long long ok = buf[tid ^ j];
            pb ^= 1;
            bool takeMin = (((tid & j) == 0) == up);
            if ((key > ok) == takeMin) key = ok;
        }
        #pragma unroll
        for (int j = ((k >> 1) < 16 ? (k >> 1) : 16); j >= 1; j >>= 1) {
            unsigned long long ok = __shfl_xor_sync(0xffffffffu, key, j);
            bool takeMin = (((tid & j) == 0) == up);
            if ((key > ok) == takeMin) key = ok;
        }
    }
    int m = (int)(key & 1023u);
    g_perm[b][tid]  = m;
    g_psort[b][tid] = g_p[b][m];
}

// ---------------------------------------------------------------------------
// K2b: suffix scan over xg (R9 form) + per-pixel binsearch -> g_k.
// Each thread already loads psort[4tid..4tid+3]; those float4s rebuild the
// full sorted array in smem for free. grid (16,8): 256 px searched per block.
// ---------------------------------------------------------------------------
__global__ void __launch_bounds__(256) k2_scan() {
    __shared__ float sm1[4][8], sm2[4][8];
    __shared__ float sps[1024];
    const int b = blockIdx.y, ig = blockIdx.x;
    const int tid = threadIdx.x, lane = tid & 31, w = tid >> 5;
    const int j0 = 4 * tid;

    if (tid == 0) {
        float2* z = &g_S12[b][1024][ig * 4];
        *(float4*)z       = make_float4(0.f, 0.f, 0.f, 0.f);
        *(float4*)(z + 2) = make_float4(0.f, 0.f, 0.f, 0.f);
    }

    const int4   pm = ((const int4*)g_perm[b])[tid];
    const float4 ps = ((const float4*)g_psort[b])[tid];
    *(float4*)&sps[j0] = ps;          // rebuild sorted array in smem (free)

    float4 v0 = *(const float4*)&g_xg[b][pm.x][ig * 4];
    float4 v1 = *(const float4*)&g_xg[b][pm.y][ig * 4];
    float4 v2 = *(const float4*)&g_xg[b][pm.z][ig * 4];
    float4 v3 = *(const float4*)&g_xg[b][pm.w][ig * 4];
    float vv[4][4] = {{v0.x, v0.y, v0.z, v0.w}, {v1.x, v1.y, v1.z, v1.w},
                      {v2.x, v2.y, v2.z, v2.w}, {v3.x, v3.y, v3.z, v3.w}};
    float pp[4] = {ps.x, ps.y, ps.z, ps.w};

    float s1[4], s2[4];
    #pragma unroll
    for (int c = 0; c < 4; c++) {
        s1[c] = vv[0][c] + vv[1][c] + vv[2][c] + vv[3][c];
        s2[c] = fmaf(pp[0], vv[0][c], fmaf(pp[1], vv[1][c],
                fmaf(pp[2], vv[2][c], pp[3] * vv[3][c])));
    }

    #pragma unroll
    for (int d = 1; d < 32; d <<= 1) {
        bool take = (lane + d < 32);
        #pragma unroll
        for (int c = 0; c < 4; c++) {
            float t1 = __shfl_down_sync(0xffffffffu, s1[c], d);
            float t2 = __shfl_down_sync(0xffffffffu, s2[c], d);
            if (take) { s1[c] += t1; s2[c] += t2; }
        }
    }
    if (lane == 0) {
        #pragma unroll
        for (int c = 0; c < 4; c++) { sm1[c][w] = s1[c]; sm2[c][w] = s2[c]; }
    }
    __syncthreads();
    #pragma unroll
    for (int c = 0; c < 4; c++) {
        float c1 = 0.f, c2 = 0.f;
        #pragma unroll
        for (int w2i = 0; w2i < 8; w2i++)
            if (w2i > w) { c1 += sm1[c][w2i]; c2 += sm2[c][w2i]; }
        s1[c] += c1; s2[c] += c2;
    }

    float2* base = &g_S12[b][j0][ig * 4];
    #pragma unroll
    for (int k = 0; k < 4; k++) {
        float4 oa = make_float4(s1[0], s2[0], s1[1], s2[1]);
        float4 ob = make_float4(s1[2], s2[2], s1[3], s2[3]);
        float2* dst = base + (long)k * 64;
        *(float4*)dst       = oa;
        *(float4*)(dst + 2) = ob;
        if (k < 3) {
            #pragma unroll
            for (int c = 0; c < 4; c++) {
                s1[c] -= vv[k][c];
                s2[c] = fmaf(-pp[k], vv[k][c], s2[c]);
            }
        }
    }

    // ---- per-pixel binsearch: block ig covers pixels [ig*256, ig*256+256) ----
    {
        int n = ig * 256 + tid;
        float keyn = -g_t[b][n];
        int lo = 0, hi = 1024;
        while (lo < hi) { int mid = (lo + hi) >> 1; if (sps[mid] > keyn) hi = mid; else lo = mid + 1; }
        g_k[b][n] = (unsigned short)lo;
    }
}

// ---------------------------------------------------------------------------
// K3: warp-specialized pipeline, NO binsearch (uses g_k), no psort/t stage.
//     512 threads: warps 0-7 consume (MMA+epi), 8-15 produce (gather+ybuild).
//     Double-buffered 64-px tiles, 128 px/block, grid (32,8)=256 blocks.
//     (R15 verbatim)
// ---------------------------------------------------------------------------
#define W2S 36
#define YB 69
__global__ void __launch_bounds__(512, 2)
k3_out(const float* __restrict__ x,
       const float* __restrict__ b2,
       const float* __restrict__ bg, const float* __restrict__ bb,
       const float* __restrict__ bm, const float* __restrict__ bv,
       float* __restrict__ out) {
    extern __shared__ float sm[];
    unsigned* sW2b = (unsigned*)sm;              // 128*36 = 4608
    unsigned* sYb  = sW2b + 128 * W2S;           // 2 * 32*69 = 4416
    float*    sA   = (float*)(sYb + 2 * 32 * YB);// 128
    float*    sB   = sA + 128;                   // 128

    const int tid = threadIdx.x;
    const int b   = blockIdx.y;
    const int n00 = blockIdx.x * 128;
    const bool producer = tid >= 256;

    if (!producer) {
        const uint4* w2b4 = (const uint4*)g_w2b;     // 1024 uint4
        #pragma unroll
        for (int k = 0; k < 4; k++) {
            int v = tid + k * 256;
            int co = v >> 3, q4 = v & 7;
            *(uint4*)&sW2b[co * W2S + q4 * 4] = w2b4[v];
        }
        if (tid < 128) {
            float inv = rsqrtf(bv[tid] + 1e-5f);
            float al  = bg[tid] * inv;
            sA[tid] = al;
            sB[tid] = (b2[tid] - bm[tid]) * al + bb[tid];
        }
    } else {
        int pt = tid - 256;
        int n = pt >> 2, q = pt & 3;
        float t = g_t[b][n00 + n];
        int lo = g_k[b][n00 + n];
        const float4* s4 = (const float4*)&g_S12[b][lo][q * 16];
        unsigned* dst = sYb;
        #pragma unroll
        for (int r = 0; r < 8; r++) {
            float4 s = s4[r];
            float y0 = fmaf(t, s.x, s.y) * (1.0f / 1024.0f);
            float y1 = fmaf(t, s.z, s.w) * (1.0f / 1024.0f);
            dst[(q * 8 + r) * YB + n] = pbf2(y0, y1);
        }
    }
    __syncthreads();

    const int w    = tid >> 5;
    const int lane = tid & 31;
    const int g    = lane >> 2;
    const int m4   = lane & 3;

    #pragma unroll 1
    for (int tt = 0; tt < 2; tt++) {
        if (!producer) {
            const unsigned* buf = sYb + (tt & 1) * 32 * YB;
            const int ocb = w * 16;
            float acc[8][4];
            #pragma unroll
            for (int t = 0; t < 8; t++)
                #pragma unroll
                for (int r = 0; r < 4; r++) acc[t][r] = 0.f;

            #pragma unroll
            for (int s = 0; s < 4; s++) {
                const int ii0 = s * 8;
                unsigned a0 = sW2b[(ocb + g)     * W2S + ii0 + m4];
                unsigned a1 = sW2b[(ocb + g + 8) * W2S + ii0 + m4];
                unsigned a2 = sW2b[(ocb + g)     * W2S + ii0 + 4 + m4];
                unsigned a3 = sW2b[(ocb + g + 8) * W2S + ii0 + 4 + m4];
                #pragma unroll
                for (int t = 0; t < 8; t++) {
                    unsigned b0 = buf[(ii0 + m4)     * YB + t * 8 + g];
                    unsigned b1 = buf[(ii0 + 4 + m4) * YB + t * 8 + g];
                    mma16816(acc[t], a0, a1, a2, a3, b0, b1);
                }
            }

            const int co0 = ocb + g, co1 = ocb + g + 8;
            const float A0 = sA[co0], B0 = sB[co0];
            const float A1 = sA[co1], B1 = sB[co1];
            const int base0 = ((b * 128 + co0) << 12) + n00 + tt * 64;
            const int base1 = ((b * 128 + co1) << 12) + n00 + tt * 64;
            #pragma unroll
            for (int t = 0; t < 8; t++) {
                int n = t * 8 + 2 * m4;
                float2 x0 = *(const float2*)&x[base0 + n];
                float2 x1 = *(const float2*)&x[base1 + n];
                float2 o0, o1;
                o0.x = fmaf(acc[t][0], A0, B0) + x0.x;
                o0.y = fmaf(acc[t][1], A0, B0) + x0.y;
                o1.x = fmaf(acc[t][2], A1, B1) + x1.x;
                o1.y = fmaf(acc[t][3], A1, B1) + x1.y;
                *(float2*)&out[base0 + n] = o0;
                *(float2*)&out[base1 + n] = o1;
            }
        } else if (tt == 0) {
            int pt = tid - 256;
            int n = pt >> 2, q = pt & 3;
            float t = g_t[b][n00 + 64 + n];
            int lo = g_k[b][n00 + 64 + n];
            const float4* s4 = (const float4*)&g_S12[b][lo][q * 16];
            unsigned* dst = sYb + 32 * YB;
            #pragma unroll
            for (int r = 0; r < 8; r++) {
                float4 s = s4[r];
                float y0 = fmaf(t, s.x, s.y) * (1.0f / 1024.0f);
                float y1 = fmaf(t, s.z, s.w) * (1.0f / 1024.0f);
                dst[(q * 8 + r) * YB + n] = pbf2(y0, y1);
            }
        }
        __syncthreads();
    }
}

// ---------------------------------------------------------------------------
extern "C" void kernel_launch(void* const* d_in, const int* in_sizes, int n_in,
                              void* d_out, int out_size) {
    const float* x  = (const float*)d_in[0];
    const float* w1 = (const float*)d_in[1];
    const float* b1 = (const float*)d_in[2];
    const float* w3 = (const float*)d_in[3];
    const float* b3 = (const float*)d_in[4];
    const float* w4 = (const float*)d_in[5];
    const float* b4 = (const float*)d_in[6];
    const float* w5 = (const float*)d_in[7];
    const float* w2 = (const float*)d_in[8];
    const float* b2 = (const float*)d_in[9];
    const float* bg = (const float*)d_in[10];
    const float* bb = (const float*)d_in[11];
    const float* bm = (const float*)d_in[12];
    const float* bv = (const float*)d_in[13];
    float* out = (float*)d_out;

    const int k1_smem = (128 * SWS + 64 * SXS) * 4 + (128 + 64 + 132 + 128) * 4;
    const int k3_smem = (128 * W2S + 2 * 32 * YB) * 4 + (128 + 128) * 4;
    cudaFuncSetAttribute(k1_conv, cudaFuncAttributeMaxDynamicSharedMemorySize, k1_smem);
    cudaFuncSetAttribute(k3_out,  cudaFuncAttributeMaxDynamicSharedMemorySize, k3_smem);

    k1_conv<<<dim3(32, 8), 256, k1_smem>>>(x, w1, b1, w3, b3, w4, b4, w5);
    k2_sort<<<8, 1024>>>(w2);
    k2_scan<<<dim3(16, 8), 256>>>();
    k3_out<<<dim3(32, 8), 512, k3_smem>>>(x, b2, bg, bb, bm, bv, out);
}

// round 17
// speedup vs baseline: 1.1742x; 1.0464x over previous
#include <cuda_runtime.h>
#include <cuda_bf16.h>

// B=8, C=128, IC=64, H=W=64, N=4096, M=1024 (pooled 32x32)

__device__ float g_p[8][1024];
__device__ float g_t[8][4096];
__device__ float g_xg[8][1024][64];
__device__ float g_psort[8][1024];
__device__ int   g_perm[8][1024];
__device__ unsigned short g_k[8][4096];   // precomputed binsearch result per pixel
__device__ unsigned g_S12b[8][1025][64];  // packed bf16x2 (S1,S2) per channel
__device__ unsigned g_w2b[4096];          // w2 packed bf16x2 [co][ii]

// ---- helpers --------------------------------------------------------------
__device__ __forceinline__ unsigned pbf2(float lo, float hi) {
    unsigned r; asm("cvt.rn.bf16x2.f32 %0, %1, %2;" : "=r"(r) : "f"(hi), "f"(lo));
    return r;
}
__device__ __forceinline__ float2 ubf2f(unsigned u) {
    __nv_bfloat162 h = *reinterpret_cast<__nv_bfloat162*>(&u);
    return __bfloat1622float2(h);
}
__device__ __forceinline__ void mma16816(float* d, unsigned a0, unsigned a1,
                                         unsigned a2, unsigned a3,
                                         unsigned b0, unsigned b1) {
    asm("mma.sync.aligned.m16n8k16.row.col.f32.bf16.bf16.f32 "
        "{%0,%1,%2,%3}, {%4,%5,%6,%7}, {%8,%9}, {%0,%1,%2,%3};"
        : "+f"(d[0]), "+f"(d[1]), "+f"(d[2]), "+f"(d[3])
        : "r"(a0), "r"(a1), "r"(a2), "r"(a3), "r"(b0), "r"(b1));
}

// ---------------------------------------------------------------------------
// K1: fused conv1+conv4 via bf16 mma.sync, in-register maxpool,
//     + folded conv3 scalar t (wtp folded per block).  (R9 verbatim)
// ---------------------------------------------------------------------------
#define SWS 68
#define SXS 136
__global__ void __launch_bounds__(256, 2)
k1_conv(const float* __restrict__ x,
        const float* __restrict__ w1, const float* __restrict__ b1,
        const float* __restrict__ w3, const float* __restrict__ b3,
        const float* __restrict__ w4, const float* __restrict__ b4,
        const float* __restrict__ w5) {
    extern __shared__ unsigned smu[];
    unsigned* sWb  = smu;                    // 128*68
    unsigned* sXb  = smu + 128 * SWS;        // 64*136
    float* sBias = (float*)(sXb + 64 * SXS); // 128
    float* sWp   = sBias + 128;              // 64
    float* sWtp  = sWp + 64;                 // 132
    float* sPred = sWtp + 132;               // 4*32

    const int tid = threadIdx.x;
    const int pr  = blockIdx.x;
    const int b   = blockIdx.y;

    const float4* w1v = (const float4*)w1;
    const float4* w4v = (const float4*)w4;
    #pragma unroll
    for (int k = 0; k < 16; k++) {
        int v  = tid + k * 256;
        int oc = v >> 5, c4 = v & 31;
        float4 f = (oc < 64) ? w1v[oc * 32 + c4] : w4v[(oc - 64) * 32 + c4];
        *(uint2*)&sWb[oc * SWS + c4 * 2] = make_uint2(pbf2(f.x, f.y), pbf2(f.z, f.w));
    }
    const float4* xv = (const float4*)x;
    #pragma unroll
    for (int it = 0; it < 8; it++) {
        int v   = tid + it * 256;
        int cc  = v >> 5, u = v & 31;
        int r01 = u >> 4, c4 = u & 15;
        float4 fa = xv[((b * 128 + 2 * cc) * 64 + (2 * pr + r01)) * 16 + c4];
        float4 fb = xv[((b * 128 + 2 * cc + 1) * 64 + (2 * pr + r01)) * 16 + c4];
        uint4 q;
        q.x = pbf2(fa.x, fb.x); q.y = pbf2(fa.y, fb.y);
        q.z = pbf2(fa.z, fb.z); q.w = pbf2(fa.w, fb.w);
        *(uint4*)&sXb[cc * SXS + r01 * 64 + c4 * 4] = q;
    }
    if (tid < 128) {
        float acc = 0.f;
        #pragma unroll 16
        for (int i = 0; i < 64; i++) acc = fmaf(w5[i], w3[i * 128 + tid], acc);
        sWtp[tid] = acc;
        sBias[tid] = (tid < 64) ? b1[tid] : b4[tid - 64];
    } else if (tid < 160) {
        int l = tid - 128;
        float s = fmaf(w5[l], b3[l], w5[l + 32] * b3[l + 32]);
        #pragma unroll
        for (int d = 16; d >= 1; d >>= 1)
            s += __shfl_xor_sync(0xffffffffu, s, d);
        if (l == 0) sWtp[128] = s;
    }
    if (tid < 64) sWp[tid] = w5[64 + tid];
    __syncthreads();

    const int w    = tid >> 5;
    const int lane = tid & 31;
    const int g    = lane >> 2;
    const int m4   = lane & 3;
    const int ocb  = w * 16;

    float acc[16][4];
    #pragma unroll
    for (int t = 0; t < 16; t++)
        #pragma unroll
        for (int r = 0; r < 4; r++) acc[t][r] = 0.f;

    #pragma unroll
    for (int s = 0; s < 8; s++) {
        const int cc0 = s * 8;
        unsigned a0 = sWb[(ocb + g)     * SWS + cc0 + m4];
        unsigned a1 = sWb[(ocb + g + 8) * SWS + cc0 + m4];
        unsigned a2 = sWb[(ocb + g)     * SWS + cc0 + 4 + m4];
        unsigned a3 = sWb[(ocb + g + 8) * SWS + cc0 + 4 + m4];
        #pragma unroll
        for (int t = 0; t < 16; t++) {
            unsigned b0 = sXb[(cc0 + m4)     * SXS + t * 8 + g];
            unsigned b1 = sXb[(cc0 + 4 + m4) * SXS + t * 8 + g];
            mma16816(acc[t], a0, a1, a2, a3, b0, b1);
        }
    }

    if (tid < 128) {
        float a = sWtp[128];
        #pragma unroll 8
        for (int cc = 0; cc < 64; cc++) {
            unsigned u = sXb[cc * SXS + tid];
            float2 f = ubf2f(u);
            a = fmaf(sWtp[2 * cc], f.x, a);
            a = fmaf(sWtp[2 * cc + 1], f.y, a);
        }
        int n = (2 * pr + (tid >> 6)) * 64 + (tid & 63);
        g_t[b][n] = a;
    }

    float pg[8], pg8[8];
    #pragma unroll
    for (int t = 0; t < 8; t++) {
        pg[t]  = fmaxf(fmaxf(acc[t][0], acc[t][1]), fmaxf(acc[t + 8][0], acc[t + 8][1]));
        pg8[t] = fmaxf(fmaxf(acc[t][2], acc[t][3]), fmaxf(acc[t + 8][2], acc[t + 8][3]));
    }

    if (w < 4) {  // xg path: oc 0..63
        int oc0 = ocb + g, oc1 = ocb + g + 8;
        float b0v = sBias[oc0], b1v = sBias[oc1];
        #pragma unroll
        for (int t = 0; t < 8; t++) {
            int mb = pr * 32 + t * 4 + m4;
            g_xg[b][mb][oc0] = pg[t]  + b0v;
            g_xg[b][mb][oc1] = pg8[t] + b1v;
        }
    } else {      // p path
        int oc0 = ocb + g, oc1 = ocb + g + 8;
        float wp0 = sWp[oc0 - 64], wp1 = sWp[oc1 - 64];
        float b0v = sBias[oc0], b1v = sBias[oc1];
        float part[8];
        #pragma unroll
        for (int t = 0; t < 8; t++)
            part[t] = fmaf(wp0, pg[t] + b0v, wp1 * (pg8[t] + b1v));
        #pragma unroll
        for (int d = 4; d < 32; d <<= 1) {
            #pragma unroll
            for (int t = 0; t < 8; t++)
                part[t] += __shfl_xor_sync(0xffffffffu, part[t], d);
        }
        if (lane < 4) {
            #pragma unroll
            for (int t = 0; t < 8; t++)
                sPred[(w - 4) * 32 + t * 4 + lane] = part[t];
        }
    }
    __syncthreads();
    if (tid < 32) {
        float pv = sPred[tid] + sPred[32 + tid] + sPred[64 + tid] + sPred[96 + tid];
        g_p[b][pr * 32 + tid] = pv;
    }
}

// ---------------------------------------------------------------------------
// K2a: bitonic sort (ping-pong smem) + w2 bf16 pack [co][ii]  (R9 verbatim)
// ---------------------------------------------------------------------------
__global__ void __launch_bounds__(1024) k2_sort(const float* __restrict__ w2) {
    __shared__ unsigned long long skA[1024], skB[1024];
    const int b = blockIdx.x, tid = threadIdx.x;

    {
        int u = b * 512 + tid;
        if (tid < 512) {
            float2 f = ((const float2*)w2)[u];
            g_w2b[u] = pbf2(f.x, f.y);
        }
    }

    float v = g_p[b][tid];
    unsigned u = __float_as_uint(v);
    u = (u & 0x80000000u) ? ~u : (u | 0x80000000u);
    unsigned long long key = ((unsigned long long)u << 32) | (unsigned)tid;

    int pb = 0;
    #pragma unroll
    for (int k = 2; k <= 1024; k <<= 1) {
        const bool up = ((tid & k) == 0);
        for (int j = k >> 1; j >= 32; j >>= 1) {
            unsigned long long* buf = pb ? skB : skA;
            buf[tid] = key;
            __syncthreads();
            unsigned long long ok = buf[tid ^ j];
            pb ^= 1;
            bool takeMin = (((tid & j) == 0) == up);
            if ((key > ok) == takeMin) key = ok;
        }
        #pragma unroll
        for (int j = ((k >> 1) < 16 ? (k >> 1) : 16); j >= 1; j >>= 1) {
            unsigned long long ok = __shfl_xor_sync(0xffffffffu, key, j);
            bool takeMin = (((tid & j) == 0) == up);
            if ((key > ok) == takeMin) key = ok;
        }
    }
    int m = (int)(key & 1023u);
    g_perm[b][tid]  = m;
    g_psort[b][tid] = g_p[b][m];
}

// ---------------------------------------------------------------------------
// K2b: suffix scan over xg + per-pixel binsearch -> g_k.
// Writes PACKED bf16x2 (S1,S2) table: one uint4 per 4 channels per row.
// ---------------------------------------------------------------------------
__global__ void __launch_bounds__(256) k2_scan() {
    __shared__ float sm1[4][8], sm2[4][8];
    __shared__ float sps[1024];
    const int b = blockIdx.y, ig = blockIdx.x;
    const int tid = threadIdx.x, lane = tid & 31, w = tid >> 5;
    const int j0 = 4 * tid;

    if (tid == 0)
        *(uint4*)&g_S12b[b][1024][ig * 4] = make_uint4(0u, 0u, 0u, 0u);

    const int4   pm = ((const int4*)g_perm[b])[tid];
    const float4 ps = ((const float4*)g_psort[b])[tid];
    *(float4*)&sps[j0] = ps;          // rebuild sorted array in smem (free)

    float4 v0 = *(const float4*)&g_xg[b][pm.x][ig * 4];
    float4 v1 = *(const float4*)&g_xg[b][pm.y][ig * 4];
    float4 v2 = *(const float4*)&g_xg[b][pm.z][ig * 4];
    float4 v3 = *(const float4*)&g_xg[b][pm.w][ig * 4];
    float vv[4][4] = {{v0.x, v0.y, v0.z, v0.w}, {v1.x, v1.y, v1.z, v1.w},
                      {v2.x, v2.y, v2.z, v2.w}, {v3.x, v3.y, v3.z, v3.w}};
    float pp[4] = {ps.x, ps.y, ps.z, ps.w};

    float s1[4], s2[4];
    #pragma unroll
    for (int c = 0; c < 4; c++) {
        s1[c] = vv[0][c] + vv[1][c] + vv[2][c] + vv[3][c];
        s2[c] = fmaf(pp[0], vv[0][c], fmaf(pp[1], vv[1][c],
                fmaf(pp[2], vv[2][c], pp[3] * vv[3][c])));
    }

    #pragma unroll
    for (int d = 1; d < 32; d <<= 1) {
        bool take = (lane + d < 32);
        #pragma unroll
        for (int c = 0; c < 4; c++) {
            float t1 = __shfl_down_sync(0xffffffffu, s1[c], d);
            float t2 = __shfl_down_sync(0xffffffffu, s2[c], d);
            if (take) { s1[c] += t1; s2[c] += t2; }
        }
    }
    if (lane == 0) {
        #pragma unroll
        for (int c = 0; c < 4; c++) { sm1[c][w] = s1[c]; sm2[c][w] = s2[c]; }
    }
    __syncthreads();
    #pragma unroll
    for (int c = 0; c < 4; c++) {
        float c1 = 0.f, c2 = 0.f;
        #pragma unroll
        for (int w2i = 0; w2i < 8; w2i++)
            if (w2i > w) { c1 += sm1[c][w2i]; c2 += sm2[c][w2i]; }
        s1[c] += c1; s2[c] += c2;
    }

    unsigned* base = &g_S12b[b][j0][ig * 4];
    #pragma unroll
    for (int k = 0; k < 4; k++) {
        uint4 o;
        o.x = pbf2(s1[0], s2[0]);
        o.y = pbf2(s1[1], s2[1]);
        o.z = pbf2(s1[2], s2[2]);
        o.w = pbf2(s1[3], s2[3]);
        *(uint4*)(base + (long)k * 64) = o;
        if (k < 3) {
            #pragma unroll
            for (int c = 0; c < 4; c++) {
                s1[c] -= vv[k][c];
                s2[c] = fmaf(-pp[k], vv[k][c], s2[c]);
            }
        }
    }

    // ---- per-pixel binsearch: block ig covers pixels [ig*256, ig*256+256) ----
    {
        int n = ig * 256 + tid;
        float keyn = -g_t[b][n];
        int lo = 0, hi = 1024;
        while (lo < hi) { int mid = (lo + hi) >> 1; if (sps[mid] > keyn) hi = mid; else lo = mid + 1; }
        g_k[b][n] = (unsigned short)lo;
    }
}

// ---------------------------------------------------------------------------
// K3: warp-specialized pipeline over bf16 S table.  (R16 skeleton)
//     512 threads: warps 0-7 consume (MMA+epi), 8-15 produce (gather+ybuild).
//     Double-buffered 64-px tiles, 128 px/block, grid (32,8)=256 blocks.
// ---------------------------------------------------------------------------
#define W2S 36
#define YB 69
__global__ void __launch_bounds__(512, 2)
k3_out(const float* __restrict__ x,
       const float* __restrict__ b2,
       const float* __restrict__ bg, const float* __restrict__ bb,
       const float* __restrict__ bm, const float* __restrict__ bv,
       float* __restrict__ out) {
    extern __shared__ float sm[];
    unsigned* sW2b = (unsigned*)sm;              // 128*36 = 4608
    unsigned* sYb  = sW2b + 128 * W2S;           // 2 * 32*69 = 4416
    float*    sA   = (float*)(sYb + 2 * 32 * YB);// 128
    float*    sB   = sA + 128;                   // 128

    const int tid = threadIdx.x;
    const int b   = blockIdx.y;
    const int n00 = blockIdx.x * 128;
    const bool producer = tid >= 256;

    if (!producer) {
        const uint4* w2b4 = (const uint4*)g_w2b;     // 1024 uint4
        #pragma unroll
        for (int k = 0; k < 4; k++) {
            int v = tid + k * 256;
            int co = v >> 3, q4 = v & 7;
            *(uint4*)&sW2b[co * W2S + q4 * 4] = w2b4[v];
        }
        if (tid < 128) {
            float inv = rsqrtf(bv[tid] + 1e-5f);
            float al  = bg[tid] * inv;
            sA[tid] = al;
            sB[tid] = (b2[tid] - bm[tid]) * al + bb[tid];
        }
    } else {
        // prologue: fill tile 0 into buf 0 via packed gather
        int pt = tid - 256;
        int n = pt >> 2, q = pt & 3;
        float t = g_t[b][n00 + n];
        int lo = g_k[b][n00 + n];
        const uint4* s4 = (const uint4*)&g_S12b[b][lo][q * 16];
        unsigned* dst = sYb;
        #pragma unroll
        for (int r4 = 0; r4 < 4; r4++) {
            uint4 u = s4[r4];
            float2 fa = ubf2f(u.x), fb = ubf2f(u.y), fc = ubf2f(u.z), fd = ubf2f(u.w);
            float ya0 = fmaf(t, fa.x, fa.y) * (1.0f / 1024.0f);
            float ya1 = fmaf(t, fb.x, fb.y) * (1.0f / 1024.0f);
            float yb0 = fmaf(t, fc.x, fc.y) * (1.0f / 1024.0f);
            float yb1 = fmaf(t, fd.x, fd.y) * (1.0f / 1024.0f);
            dst[(q * 8 + 2 * r4)     * YB + n] = pbf2(ya0, ya1);
            dst[(q * 8 + 2 * r4 + 1) * YB + n] = pbf2(yb0, yb1);
        }
    }
    __syncthreads();

    const int w    = tid >> 5;
    const int lane = tid & 31;
    const int g    = lane >> 2;
    const int m4   = lane & 3;

    #pragma unroll 1
    for (int tt = 0; tt < 2; tt++) {
        if (!producer) {
            const unsigned* buf = sYb + (tt & 1) * 32 * YB;
            const int ocb = w * 16;
            float acc[8][4];
            #pragma unroll
            for (int t = 0; t < 8; t++)
                #pragma unroll
                for (int r = 0; r < 4; r++) acc[t][r] = 0.f;

            #pragma unroll
            for (int s = 0; s < 4; s++) {
                const int ii0 = s * 8;
                unsigned a0 = sW2b[(ocb + g)     * W2S + ii0 + m4];
                unsigned a1 = sW2b[(ocb + g + 8) * W2S + ii0 + m4];
                unsigned a2 = sW2b[(ocb + g)     * W2S + ii0 + 4 + m4];
                unsigned a3 = sW2b[(ocb + g + 8) * W2S + ii0 + 4 + m4];
                #pragma unroll
                for (int t = 0; t < 8; t++) {
                    unsigned b0 = buf[(ii0 + m4)     * YB + t * 8 + g];
                    unsigned b1 = buf[(ii0 + 4 + m4) * YB + t * 8 + g];
                    mma16816(acc[t], a0, a1, a2, a3, b0, b1);
                }
            }

            const int co0 = ocb + g, co1 = ocb + g + 8;
            const float A0 = sA[co0], B0 = sB[co0];
            const float A1 = sA[co1], B1 = sB[co1];
            const int base0 = ((b * 128 + co0) << 12) + n00 + tt * 64;
            const int base1 = ((b * 128 + co1) << 12) + n00 + tt * 64;
            #pragma unroll
            for (int t = 0; t < 8; t++) {
                int n = t * 8 + 2 * m4;
                float2 x0 = *(const float2*)&x[base0 + n];
                float2 x1 = *(const float2*)&x[base1 + n];
                float2 o0, o1;
                o0.x = fmaf(acc[t][0], A0, B0) + x0.x;
                o0.y = fmaf(acc[t][1], A0, B0) + x0.y;
                o1.x = fmaf(acc[t][2], A1, B1) + x1.x;
                o1.y = fmaf(acc[t][3], A1, B1) + x1.y;
                *(float2*)&out[base0 + n] = o0;
                *(float2*)&out[base1 + n] = o1;
            }
        } else if (tt == 0) {
            // produce tile 1 into buf 1 via packed gather
            int pt = tid - 256;
            int n = pt >> 2, q = pt & 3;
            float t = g_t[b][n00 + 64 + n];
            int lo = g_k[b][n00 + 64 + n];
            const uint4* s4 = (const uint4*)&g_S12b[b][lo][q * 16];
            unsigned* dst = sYb + 32 * YB;
            #pragma unroll
            for (int r4 = 0; r4 < 4; r4++) {
                uint4 u = s4[r4];
                float2 fa = ubf2f(u.x), fb = ubf2f(u.y), fc = ubf2f(u.z), fd = ubf2f(u.w);
                float ya0 = fmaf(t, fa.x, fa.y) * (1.0f / 1024.0f);
                float ya1 = fmaf(t, fb.x, fb.y) * (1.0f / 1024.0f);
                float yb0 = fmaf(t, fc.x, fc.y) * (1.0f / 1024.0f);
                float yb1 = fmaf(t, fd.x, fd.y) * (1.0f / 1024.0f);
                dst[(q * 8 + 2 * r4)     * YB + n] = pbf2(ya0, ya1);
                dst[(q * 8 + 2 * r4 + 1) * YB + n] = pbf2(yb0, yb1);
            }
        }
        __syncthreads();
    }
}

// ---------------------------------------------------------------------------
extern "C" void kernel_launch(void* const* d_in, const int* in_sizes, int n_in,
                              void* d_out, int out_size) {
    const float* x  = (const float*)d_in[0];
    const float* w1 = (const float*)d_in[1];
    const float* b1 = (const float*)d_in[2];
    const float* w3 = (const float*)d_in[3];
    const float* b3 = (const float*)d_in[4];
    const float* w4 = (const float*)d_in[5];
    const float* b4 = (const float*)d_in[6];
    const float* w5 = (const float*)d_in[7];
    const float* w2 = (const float*)d_in[8];
    const float* b2 = (const float*)d_in[9];
    const float* bg = (const float*)d_in[10];
    const float* bb = (const float*)d_in[11];
    const float* bm = (const float*)d_in[12];
    const float* bv = (const float*)d_in[13];
    float* out = (float*)d_out;

    const int k1_smem = (128 * SWS + 64 * SXS) * 4 + (128 + 64 + 132 + 128) * 4;
    const int k3_smem = (128 * W2S + 2 * 32 * YB) * 4 + (128 + 128) * 4;
    cudaFuncSetAttribute(k1_conv, cudaFuncAttributeMaxDynamicSharedMemorySize, k1_smem);
    cudaFuncSetAttribute(k3_out,  cudaFuncAttributeMaxDynamicSharedMemorySize, k3_smem);

    k1_conv<<<dim3(32, 8), 256, k1_smem>>>(x, w1, b1, w3, b3, w4, b4, w5);
    k2_sort<<<8, 1024>>>(w2);
    k2_scan<<<dim3(16, 8), 256>>>();
    k3_out<<<dim3(32, 8), 512, k3_smem>>>(x, b2, bg, bb, bm, bv, out);
}